// round 17
// baseline (speedup 1.0000x reference)
#include <cuda_runtime.h>
#include <cuda_bf16.h>
#include <math.h>
#include <stdint.h>

// Problem dims (fixed)
#define BSZ  32
#define TLEN 512
#define DIN  512
#define HN   1024
#define G4H  (4*HN)   // 4096

#define NBLK 128       // persistent grid size (1 CTA/SM)

// recurrence smem layout
#define WWORDS   18432         // 512 kk-pairs x 36 (pad) u32 per split
#define WBYTES   (WWORDS*4)    // 73,728 B per split
#define HROW     264           // staged h row stride (bf16), pad 8
#define HSPLIT   (32*HROW*2)   // 16,896 B per split per buffer
#define STGB     (2*HSPLIT)    // 33,792 B per buffer (hi+lo)
#define SOFF     (2*WBYTES)    // staging offset = 147,456
#define RSMEMB   (SOFF + 2*STGB)  // 215,040 B total
#define REDS     260           // red row stride (floats)

// GEMM staging (bytes)
#define ABYT 16384     // As: 128 rows x 128B
#define BBYT 17408     // Bs: 32 rows x 544B (136 floats, pad 8)
#define STG  (ABYT + BBYT)

// ---------------- scratch (device globals; no allocation allowed) ----------------
__device__ float g_xg[(size_t)TLEN * BSZ * G4H];   // [T][B][4H]  256 MB
__device__ float g_hseq[(size_t)BSZ * TLEN * HN];  // [B][T][H]    64 MB
__device__ uint4 g_Wbh0[NBLK * 4608];              // packed Wh0 hi
__device__ uint4 g_Wbl0[NBLK * 4608];              // packed Wh0 lo
__device__ uint4 g_Wbh1[NBLK * 4608];              // packed Wh1 hi
__device__ uint4 g_Wbl1[NBLK * 4608];              // packed Wh1 lo
__device__ uint4 g_hb4[2 * 2 * 4096];              // h bf16 [buf][split][32*1024]
__device__ unsigned g_cnt;
__device__ volatile unsigned g_gen;
__device__ float g_Atf[(size_t)16384 * 1024];      // tf32-rounded A   64 MB
__device__ float g_Btf[(size_t)1024 * G4H];        // tf32-rounded W   16 MB

// ---------------- grid-wide barrier (R5-proven) ----------------
__device__ __forceinline__ void grid_bar() {
    __threadfence();
    __syncthreads();
    if (threadIdx.x == 0) {
        unsigned my = g_gen;
        if (atomicAdd(&g_cnt, 1u) == (unsigned)(gridDim.x - 1)) {
            g_cnt = 0;
            __threadfence();
            g_gen = my + 1;
        } else {
            while (g_gen == my) { }
        }
        __threadfence();
    }
    __syncthreads();
}

// ---------------- mma helpers ----------------
__device__ __forceinline__ void mma_bf16(float* c, const unsigned* a, const unsigned* b) {
    asm volatile(
        "mma.sync.aligned.m16n8k16.row.col.f32.bf16.bf16.f32 "
        "{%0,%1,%2,%3}, {%4,%5,%6,%7}, {%8,%9}, {%0,%1,%2,%3};\n"
        : "+f"(c[0]), "+f"(c[1]), "+f"(c[2]), "+f"(c[3])
        : "r"(a[0]), "r"(a[1]), "r"(a[2]), "r"(a[3]), "r"(b[0]), "r"(b[1]));
}
__device__ __forceinline__ unsigned f2tf(float f) {
    unsigned u; asm("cvt.rna.tf32.f32 %0, %1;" : "=r"(u) : "f"(f)); return u;
}
__device__ __forceinline__ void mma_tf32(float* c, const unsigned* a, const unsigned* b) {
    asm volatile(
        "mma.sync.aligned.m16n8k8.row.col.f32.tf32.tf32.f32 "
        "{%0,%1,%2,%3}, {%4,%5,%6,%7}, {%8,%9}, {%0,%1,%2,%3};\n"
        : "+f"(c[0]), "+f"(c[1]), "+f"(c[2]), "+f"(c[3])
        : "r"(a[0]), "r"(a[1]), "r"(a[2]), "r"(a[3]), "r"(b[0]), "r"(b[1]));
}
__device__ __forceinline__ uint32_t smem_u32(const void* p) {
    uint32_t a;
    asm("{ .reg .u64 t; cvta.to.shared.u64 t, %1; cvt.u32.u64 %0, t; }"
        : "=r"(a) : "l"(p));
    return a;
}
__device__ __forceinline__ void cp16(uint32_t d, const void* s) {
    asm volatile("cp.async.cg.shared.global [%0], [%1], 16;" :: "r"(d), "l"(s));
}
__device__ __forceinline__ void cp_commit() {
    asm volatile("cp.async.commit_group;" ::: "memory");
}

// ---------------- prep: round fp32 -> tf32, A and W in one launch ----------------
__global__ void cvt_all_kernel(const float* __restrict__ inA, float* __restrict__ outA,
                               int n4a,
                               const float* __restrict__ inB, float* __restrict__ outB,
                               int n4b) {
    int i = blockIdx.x * blockDim.x + threadIdx.x;
    const float* in;
    float* out;
    if (i < n4a) { in = inA + (size_t)i * 4; out = outA + (size_t)i * 4; }
    else {
        int j = i - n4a;
        if (j >= n4b) return;
        in = inB + (size_t)j * 4; out = outB + (size_t)j * 4;
    }
    float4 v = *(const float4*)in;
    v.x = __uint_as_float(f2tf(v.x));
    v.y = __uint_as_float(f2tf(v.y));
    v.z = __uint_as_float(f2tf(v.z));
    v.w = __uint_as_float(f2tf(v.w));
    *(float4*)out = v;
}

// ---------------- prep: pack Wh -> bf16 hi/lo k-pair-interleaved ----------------
__global__ void pack_whb_kernel(const float* __restrict__ Wh,
                                uint4* __restrict__ whi, uint4* __restrict__ wlo) {
    const int nb = blockIdx.x;
    const int tid = threadIdx.x;
    uint32_t* Hi = (uint32_t*)(whi + (size_t)nb * 4608);
    uint32_t* Lo = (uint32_t*)(wlo + (size_t)nb * 4608);
#pragma unroll 4
    for (int e = 0; e < 64; e++) {
        int idx = e * 256 + tid;
        int kk = idx >> 5;
        int nl = idx & 31;
        int col = ((nl >> 3) << 10) + nb * 8 + (nl & 7);
        float w0 = Wh[(size_t)(2 * kk) * G4H + col];
        float w1 = Wh[(size_t)(2 * kk + 1) * G4H + col];
        __nv_bfloat16 h0 = __float2bfloat16_rn(w0);
        __nv_bfloat16 h1 = __float2bfloat16_rn(w1);
        __nv_bfloat16 l0 = __float2bfloat16_rn(w0 - __bfloat162float(h0));
        __nv_bfloat16 l1 = __float2bfloat16_rn(w1 - __bfloat162float(h1));
        __nv_bfloat162 ph; ph.x = h0; ph.y = h1;
        __nv_bfloat162 pl; pl.x = l0; pl.y = l1;
        Hi[kk * 36 + nl] = *(uint32_t*)&ph;
        Lo[kk * 36 + nl] = *(uint32_t*)&pl;
    }
}

// ---------------- tf32 mma GEMM (unchanged, passing) ----------------
__global__ void __launch_bounds__(256, 2) gemm_xg_cp(
    const float* __restrict__ A, const float* __restrict__ Bw,
    const float* __restrict__ bias, float* __restrict__ C, int K)
{
    extern __shared__ char gsm[];
    const uint32_t sb = smem_u32(gsm);

    const int tid = threadIdx.x;
    const int bx = blockIdx.x;
    const int by = blockIdx.y;
    const int wid = tid >> 5;
    const int lane = tid & 31;
    const int g = lane >> 2, tg = lane & 3;
    const int wm = wid & 1, wn = wid >> 1;
    const int m0w = wm * 64, n0w = wn * 32;
    const int KT = K >> 5;

    const int aR = tid >> 3, aKc = tid & 7;
    const int bR = tid >> 5, bNc = tid & 31;

    float acc[4][4][4];
#pragma unroll
    for (int a = 0; a < 4; a++)
#pragma unroll
        for (int b = 0; b < 4; b++)
#pragma unroll
            for (int cix = 0; cix < 4; cix++) acc[a][b][cix] = 0.f;

    auto issue = [&](int kt, int buf) {
        const uint32_t as = sb + buf * STG;
        const uint32_t bs = as + ABYT;
#pragma unroll
        for (int it = 0; it < 4; it++) {
            int row = it * 32 + aR;
            uint32_t doff = row * 128 + ((aKc * 16) ^ ((row & 7) << 4));
            cp16(as + doff, A + (size_t)(by * 128 + row) * K + kt * 32 + aKc * 4);
        }
#pragma unroll
        for (int it = 0; it < 4; it++) {
            int kr = it * 8 + bR;
            cp16(bs + kr * 544 + bNc * 16,
                 Bw + (size_t)(kt * 32 + kr) * G4H + bx * 128 + bNc * 4);
        }
        cp_commit();
    };

    issue(0, 0);
    for (int kt = 0; kt < KT; kt++) {
        const int buf = kt & 1;
        if (kt + 1 < KT) {
            issue(kt + 1, (kt + 1) & 1);
            asm volatile("cp.async.wait_group 1;" ::: "memory");
        } else {
            asm volatile("cp.async.wait_group 0;" ::: "memory");
        }
        __syncthreads();

        const unsigned* As = (const unsigned*)(gsm + buf * STG);
        const unsigned* Bs = (const unsigned*)(gsm + buf * STG + ABYT);
#pragma unroll
        for (int s = 0; s < 4; s++) {
            unsigned af[4][4], bf[4][2];
            const int c0 = (8 * s + tg) ^ (g << 2);
            const int c1 = c0 ^ 4;
#pragma unroll
            for (int mb = 0; mb < 4; mb++) {
                int m = m0w + mb * 16 + g;
                af[mb][0] = As[m * 32 + c0];
                af[mb][1] = As[(m + 8) * 32 + c0];
                af[mb][2] = As[m * 32 + c1];
                af[mb][3] = As[(m + 8) * 32 + c1];
            }
#pragma unroll
            for (int nb = 0; nb < 4; nb++) {
                bf[nb][0] = Bs[(8 * s + tg) * 136 + n0w + nb * 8 + g];
                bf[nb][1] = Bs[(8 * s + tg + 4) * 136 + n0w + nb * 8 + g];
            }
#pragma unroll
            for (int mb = 0; mb < 4; mb++)
#pragma unroll
                for (int nb = 0; nb < 4; nb++)
                    mma_tf32(acc[mb][nb], af[mb], bf[nb]);
        }
        __syncthreads();
    }

#pragma unroll
    for (int mb = 0; mb < 4; mb++) {
        int m1 = by * 128 + m0w + mb * 16 + g;
        int m2 = m1 + 8;
        size_t r1 = (size_t)(((m1 & 511) << 5) + (m1 >> 9)) * G4H;
        size_t r2 = (size_t)(((m2 & 511) << 5) + (m2 >> 9)) * G4H;
#pragma unroll
        for (int nb = 0; nb < 4; nb++) {
            int n = bx * 128 + n0w + nb * 8 + 2 * tg;
            float2 bb = *(const float2*)(bias + n);
            float2 o1 = { acc[mb][nb][0] + bb.x, acc[mb][nb][1] + bb.y };
            float2 o2 = { acc[mb][nb][2] + bb.x, acc[mb][nb][3] + bb.y };
            *(float2*)(C + r1 + n) = o1;
            *(float2*)(C + r2 + n) = o2;
        }
    }
}

// ---------------- persistent LSTM layer: bf16-split mma, 16 warps ----------------
// 128 blocks x 512 threads. Warp wq: ks = wq>>1 (k-slice of 128), nh = wq&1
// (n-half: nt in {2nh, 2nh+1}). Fragment math identical to R16; red layout
// unchanged (8 slices x 32 cols, each warp writes its half-columns).
extern __shared__ char r_smem[];
__global__ void __launch_bounds__(512, 1) lstm_layer_persistent(
    const float* __restrict__ xg,
    const uint4* __restrict__ whi, const uint4* __restrict__ wlo,
    __nv_bfloat16* __restrict__ hb, float* __restrict__ outb)
{
    const int tid  = threadIdx.x;
    const int lane = tid & 31;
    const int wq   = tid >> 5;        // 0..15
    const int ks   = wq >> 1;         // 0..7 (k-slice)
    const int nh   = wq & 1;          // 0..1 (n-half)
    const int g    = lane >> 2;       // 0..7
    const int t4   = lane & 3;        // 0..3
    const int nb   = blockIdx.x;

    uint32_t* Wshi = (uint32_t*)r_smem;            // [512][36] u32
    uint32_t* Wslo = Wshi + WWORDS;
    char*     stg0 = r_smem + SOFF;                // staging buf0 (hi | lo)
    char*     stg1 = stg0 + STGB;                  // staging buf1
    float*    red  = (float*)stg0;                 // [32 b][REDS] alias

    // ---- load W hi/lo into smem (once per layer) ----
    {
        const uint4* Gh = whi + (size_t)nb * 4608;
        const uint4* Gl = wlo + (size_t)nb * 4608;
        uint4* Sh = (uint4*)Wshi;
        uint4* Sl = (uint4*)Wslo;
#pragma unroll
        for (int it = 0; it < 9; it++) {
            Sh[it * 512 + tid] = Gh[it * 512 + tid];
            Sl[it * 512 + tid] = Gl[it * 512 + tid];
        }
    }
    __syncthreads();

    const int nl  = tid & 7;
    const int myn = nb * 8 + nl;              // epilogue lane's output col
    const int myb = (tid >> 3) & 31;          // epilogue lane's batch (tid<256)
    float creg = 0.f;

    for (int t = 0; t < TLEN; t++) {
        const int inb = t & 1, outbuf = inb ^ 1;
        const __nv_bfloat16* hinH = hb + inb * 65536;
        const __nv_bfloat16* hinL = hinH + 32768;
        __nv_bfloat16* houtH = hb + outbuf * 65536;
        __nv_bfloat16* houtL = houtH + 32768;
        const float* xg_t = xg + (size_t)t * BSZ * G4H;

        // epilogue lanes prefetch their 4 gate inputs
        float xvi = 0.f, xvf = 0.f, xvg = 0.f, xvo = 0.f;
        if (tid < 256) {
            const float* xp = xg_t + (size_t)myb * G4H + myn;
            xvi = xp[0];
            xvf = xp[HN];
            xvg = xp[2 * HN];
            xvo = xp[3 * HN];
        }

        float acc[2][2][4];
#pragma unroll
        for (int mt = 0; mt < 2; mt++)
#pragma unroll
            for (int n2 = 0; n2 < 2; n2++)
#pragma unroll
                for (int i = 0; i < 4; i++) acc[mt][n2][i] = 0.f;

        // prefetch quarter 0 (uint4 = 8 bf16); 1024 uint4 per split, 512 thr
        uint4 ph[2], pl[2];
#pragma unroll
        for (int it = 0; it < 2; it++) {
            int j = it * 512 + tid;
            int b = j >> 5, k8 = j & 31;
            ph[it] = __ldcg((const uint4*)hinH + b * 128 + k8);
            pl[it] = __ldcg((const uint4*)hinL + b * 128 + k8);
        }

#pragma unroll
        for (int q = 0; q < 4; q++) {
            char* sbuf = (q & 1) ? stg1 : stg0;
#pragma unroll
            for (int it = 0; it < 2; it++) {
                int j = it * 512 + tid;
                int b = j >> 5, k8 = j & 31;
                *(uint4*)(sbuf + b * 528 + k8 * 16) = ph[it];
                *(uint4*)(sbuf + HSPLIT + b * 528 + k8 * 16) = pl[it];
            }
            __syncthreads();
            if (q < 3) {
#pragma unroll
                for (int it = 0; it < 2; it++) {
                    int j = it * 512 + tid;
                    int b = j >> 5, k8 = j & 31;
                    ph[it] = __ldcg((const uint4*)hinH + b * 128 + (q + 1) * 32 + k8);
                    pl[it] = __ldcg((const uint4*)hinL + b * 128 + (q + 1) * 32 + k8);
                }
            }
            const __nv_bfloat16* shH = (const __nv_bfloat16*)sbuf;
            const __nv_bfloat16* shL = (const __nv_bfloat16*)(sbuf + HSPLIT);
#pragma unroll
            for (int c = 0; c < 2; c++) {
                const int kc  = ks * 32 + c * 16;          // bf16 col in quarter
                const int kkb = q * 128 + ks * 16 + c * 8; // global k-pair base
                unsigned ahi[2][4], alo[2][4];
                const int ab = kc + 2 * t4;
#pragma unroll
                for (int mt = 0; mt < 2; mt++) {
                    int r0 = mt * 16 + g;
                    const __nv_bfloat16* pH = shH + r0 * HROW + ab;
                    const __nv_bfloat16* pL = shL + r0 * HROW + ab;
                    ahi[mt][0] = *(const uint32_t*)(pH);
                    ahi[mt][1] = *(const uint32_t*)(pH + 8 * HROW);
                    ahi[mt][2] = *(const uint32_t*)(pH + 8);
                    ahi[mt][3] = *(const uint32_t*)(pH + 8 * HROW + 8);
                    alo[mt][0] = *(const uint32_t*)(pL);
                    alo[mt][1] = *(const uint32_t*)(pL + 8 * HROW);
                    alo[mt][2] = *(const uint32_t*)(pL + 8);
                    alo[mt][3] = *(const uint32_t*)(pL + 8 * HROW + 8);
                }
#pragma unroll
                for (int n2 = 0; n2 < 2; n2++) {
                    const int nt = nh * 2 + n2;
                    const uint32_t* wh = Wshi + (kkb + t4) * 36 + nt * 8 + g;
                    const uint32_t* wl = Wslo + (kkb + t4) * 36 + nt * 8 + g;
                    unsigned bhi[2] = { wh[0], wh[4 * 36] };
                    unsigned blo[2] = { wl[0], wl[4 * 36] };
#pragma unroll
                    for (int mt = 0; mt < 2; mt++) {
                        mma_bf16(acc[mt][n2], ahi[mt], bhi);
                        mma_bf16(acc[mt][n2], ahi[mt], blo);
                        mma_bf16(acc[mt][n2], alo[mt], bhi);
                    }
                }
            }
        }

        // ---- reduction: red[b][ks*32 + ncol] (red aliases buf0; q2 was its
        // last compute, ordered before q3's staging sync) ----
#pragma unroll
        for (int mt = 0; mt < 2; mt++) {
            int b1 = mt * 16 + g;
#pragma unroll
            for (int n2 = 0; n2 < 2; n2++) {
                int nt = nh * 2 + n2;
                int ncol = ks * 32 + nt * 8 + 2 * t4;
                float2 v1 = { acc[mt][n2][0], acc[mt][n2][1] };
                float2 v2 = { acc[mt][n2][2], acc[mt][n2][3] };
                *(float2*)&red[(size_t)b1 * REDS + ncol] = v1;
                *(float2*)&red[(size_t)(b1 + 8) * REDS + ncol] = v2;
            }
        }
        __syncthreads();

        // ---- epilogue (first 256 threads): sum 8 k-slices, gates, cell ----
        if (tid < 256) {
            float gi = xvi, gf = xvf, gg = xvg, go = xvo;
#pragma unroll
            for (int s = 0; s < 8; s++) {
                const float* rp = &red[(size_t)myb * REDS + s * 32];
                gi += rp[nl];
                gf += rp[8 + nl];
                gg += rp[16 + nl];
                go += rp[24 + nl];
            }
            float si = 1.f / (1.f + expf(-gi));
            float sf = 1.f / (1.f + expf(-gf));
            float so = 1.f / (1.f + expf(-go));
            creg = sf * creg + si * tanhf(gg);
            float hv = so * tanhf(creg);

            __nv_bfloat16 hhi = __float2bfloat16_rn(hv);
            __nv_bfloat16 hlo = __float2bfloat16_rn(hv - __bfloat162float(hhi));
            houtH[(size_t)myb * HN + myn] = hhi;
            houtL[(size_t)myb * HN + myn] = hlo;
            outb[(size_t)myb * (TLEN * HN) + (size_t)t * HN + myn] = hv;
        }

        grid_bar();   // includes threadfence: h publish ordered before release
    }
}

// ---------------- driver ----------------
extern "C" void kernel_launch(void* const* d_in, const int* in_sizes, int n_in,
                              void* d_out, int out_size) {
    const float* x   = (const float*)d_in[0];
    const float* Wx0 = (const float*)d_in[1];
    const float* Wh0 = (const float*)d_in[2];
    const float* b0  = (const float*)d_in[3];
    const float* Wx1 = (const float*)d_in[4];
    const float* Wh1 = (const float*)d_in[5];
    const float* b1  = (const float*)d_in[6];
    float* out = (float*)d_out;

    float *xg, *hseq, *atf, *btf;
    uint4 *wbh0, *wbl0, *wbh1, *wbl1, *hb4;
    cudaGetSymbolAddress((void**)&xg,   g_xg);
    cudaGetSymbolAddress((void**)&hseq, g_hseq);
    cudaGetSymbolAddress((void**)&atf,  g_Atf);
    cudaGetSymbolAddress((void**)&btf,  g_Btf);
    cudaGetSymbolAddress((void**)&wbh0, g_Wbh0);
    cudaGetSymbolAddress((void**)&wbl0, g_Wbl0);
    cudaGetSymbolAddress((void**)&wbh1, g_Wbh1);
    cudaGetSymbolAddress((void**)&wbl1, g_Wbl1);
    cudaGetSymbolAddress((void**)&hb4,  g_hb4);

    cudaFuncSetAttribute(lstm_layer_persistent,
                         cudaFuncAttributeMaxDynamicSharedMemorySize, RSMEMB);
    const int GSMEM = 2 * STG;
    cudaFuncSetAttribute(gemm_xg_cp,
                         cudaFuncAttributeMaxDynamicSharedMemorySize, GSMEM);

    // kernel-launch order chosen so ncu's #4 kernel capture = lstm0:
    //   cvt_all0(1), pack0(2), gemm0(3), lstm0(4)   [memsets don't count]
    cudaMemsetAsync(hb4, 0, 2 * 2 * 4096 * sizeof(uint4), 0);

    const int n4a0 = 16384 * DIN / 4, n4b0 = DIN * G4H / 4;
    cvt_all_kernel<<<(n4a0 + n4b0 + 255) / 256, 256>>>(x, atf, n4a0, Wx0, btf, n4b0);
    pack_whb_kernel<<<NBLK, 256>>>(Wh0, wbh0, wbl0);
    gemm_xg_cp<<<dim3(G4H / 128, 16384 / 128), 256, GSMEM>>>(atf, btf, b0, xg, DIN);
    lstm_layer_persistent<<<NBLK, 512, RSMEMB>>>(
        xg, wbh0, wbl0, (__nv_bfloat16*)hb4, hseq);

    // ---- layer 1 ----
    pack_whb_kernel<<<NBLK, 256>>>(Wh1, wbh1, wbl1);
    const int n4a1 = 16384 * HN / 4, n4b1 = HN * G4H / 4;
    cvt_all_kernel<<<(n4a1 + n4b1 + 255) / 256, 256>>>(hseq, atf, n4a1, Wx1, btf, n4b1);
    gemm_xg_cp<<<dim3(G4H / 128, 16384 / 128), 256, GSMEM>>>(atf, btf, b1, xg, HN);
    cudaMemsetAsync(hb4, 0, 2 * 2 * 4096 * sizeof(uint4), 0);
    lstm_layer_persistent<<<NBLK, 512, RSMEMB>>>(
        xg, wbh1, wbl1, (__nv_bfloat16*)hb4, out);
}